// round 3
// baseline (speedup 1.0000x reference)
#include <cuda_runtime.h>
#include <math.h>

#define NB 128
#define NT 128
#define NV 10000
#define NE 256
#define NH 1024
#define ND 128
#define NG 3072   // 3*NH

#define NBLK 128
#define KC   64
#define W_LD 1028
#define H_LD 68

typedef unsigned long long u64;

// ---------------- scratch ----------------
__device__ float g_table[(size_t)NV * NG];
__device__ float g_hs[(size_t)NB * NT * NH];
__device__ float g_d[(size_t)NB * NT * ND];
__device__ float g_logits[(size_t)NB * NT * NV];
__device__ unsigned g_barcnt;

__device__ __forceinline__ void ffma2(u64& d, u64 a, u64 b) {
    asm("fma.rn.f32x2 %0, %1, %2, %0;" : "+l"(d) : "l"(a), "l"(b));
}
__device__ __forceinline__ u64 pack2(float x) {
    u64 r; asm("mov.b64 %0, {%1, %1};" : "=l"(r) : "f"(x)); return r;
}
__device__ __forceinline__ float lo32(u64 v) { return __uint_as_float((unsigned)v); }
__device__ __forceinline__ float hi32(u64 v) { return __uint_as_float((unsigned)(v >> 32)); }

// ---------------- packed-f32x2 GEMM: C[M,N] = A[M,K] @ B[K,N] (+bias, relu) -----
// BM=BN=128, BK=16, 256 threads. Thread: rows tm0..tm0+7, cols {tn0..tn0+3, tn0+64..tn0+67}.
__global__ __launch_bounds__(256)
void gemm_f32x2(const float* __restrict__ A, int lda,
                const float* __restrict__ Bmat, int ldb,
                float* __restrict__ C, int ldc,
                int M, int N, int K,
                const float* __restrict__ bias, int relu)
{
    constexpr int BM = 128, BN = 128, BK = 16;
    __shared__ float As[BK][BM];
    __shared__ float Bs[BK][BN];

    const int tid = threadIdx.x;
    const int bm0 = blockIdx.y * BM;
    const int bn0 = blockIdx.x * BN;
    const int tn0 = (tid & 15) * 4;
    const int tm0 = (tid >> 4) * 8;

    u64 acc[8][4];
#pragma unroll
    for (int i = 0; i < 8; i++)
#pragma unroll
        for (int j = 0; j < 4; j++) acc[i][j] = 0ull;

    for (int k0 = 0; k0 < K; k0 += BK) {
        // A tile: BM x BK -> As[k][m] (transposed), float4 along K
#pragma unroll
        for (int it = 0; it < 2; it++) {
            int idx = tid + 256 * it;            // 0..511
            int m  = idx / (BK/4);
            int kk = (idx % (BK/4)) * 4;
            int gm = bm0 + m; if (gm > M-1) gm = M-1;
            float4 v = *(const float4*)&A[(size_t)gm * lda + k0 + kk];
            As[kk+0][m] = v.x; As[kk+1][m] = v.y;
            As[kk+2][m] = v.z; As[kk+3][m] = v.w;
        }
        // B tile: BK x BN, float4 along N
#pragma unroll
        for (int it = 0; it < 2; it++) {
            int idx = tid + 256 * it;
            int kk = idx / (BN/4);
            int n  = (idx % (BN/4)) * 4;
            int gn = bn0 + n; if (gn > N-4) gn = N-4;   // N%4==0 at all call sites
            float4 v = *(const float4*)&Bmat[(size_t)(k0+kk) * ldb + gn];
            *(float4*)&Bs[kk][n] = v;
        }
        __syncthreads();
#pragma unroll
        for (int kk = 0; kk < BK; kk++) {
            float4 a0 = *(const float4*)&As[kk][tm0];
            float4 a1 = *(const float4*)&As[kk][tm0 + 4];
            u64 b0 = *(const u64*)&Bs[kk][tn0];
            u64 b1 = *(const u64*)&Bs[kk][tn0 + 2];
            u64 b2 = *(const u64*)&Bs[kk][tn0 + 64];
            u64 b3 = *(const u64*)&Bs[kk][tn0 + 66];
            float a[8] = {a0.x, a0.y, a0.z, a0.w, a1.x, a1.y, a1.z, a1.w};
#pragma unroll
            for (int i = 0; i < 8; i++) {
                u64 a2 = pack2(a[i]);
                ffma2(acc[i][0], a2, b0);
                ffma2(acc[i][1], a2, b1);
                ffma2(acc[i][2], a2, b2);
                ffma2(acc[i][3], a2, b3);
            }
        }
        __syncthreads();
    }

#pragma unroll
    for (int i = 0; i < 8; i++) {
        int gm = bm0 + tm0 + i;
        if (gm >= M) continue;
#pragma unroll
        for (int j = 0; j < 4; j++) {
            int gn = bn0 + tn0 + ((j >> 1) ? 64 : 0) + (j & 1) * 2;
            float v0 = lo32(acc[i][j]);
            float v1 = hi32(acc[i][j]);
            if (gn < N) {
                float v = v0;
                if (bias) v += bias[gn];
                if (relu) v = fmaxf(v, 0.0f);
                C[(size_t)gm * ldc + gn] = v;
            }
            if (gn + 1 < N) {
                float v = v1;
                if (bias) v += bias[gn + 1];
                if (relu) v = fmaxf(v, 0.0f);
                C[(size_t)gm * ldc + gn + 1] = v;
            }
        }
    }
}

// ---------------- persistent GRU ------------------------------------------------
__global__ void reset_bar() { g_barcnt = 0u; }

#define W_FLOATS (24 * W_LD)
#define HBUF_FLOATS (128 * H_LD)
#define TOK_FLOATS 128
#define PERSIST_SMEM_BYTES ((W_FLOATS + 2 * HBUF_FLOATS + TOK_FLOATS) * 4)

__device__ __forceinline__ float fsigmoid(float x) {
    return 1.0f / (1.0f + __expf(-x));
}
__device__ __forceinline__ float ftanh(float x) {
    return 1.0f - __fdividef(2.0f, __expf(2.0f * x) + 1.0f);
}

__global__ __launch_bounds__(256, 1)
void gru_persist(const int* __restrict__ tokens,
                 const float* __restrict__ gru_rk,
                 const float* __restrict__ br)
{
    extern __shared__ float sm[];
    float* w_s = sm;                          // [24][W_LD]
    float* h_b = sm + W_FLOATS;               // 2 x [128][H_LD]
    int*   tok_s = (int*)(sm + W_FLOATS + 2 * HBUF_FLOATS);  // [128]

    const int tid = threadIdx.x;
    const int bid = blockIdx.x;
    const int j   = tid & 7;
    const int rg4 = tid >> 3;
    const int jb  = bid * 8;

    for (int idx = tid; idx < 1024 * 24; idx += 256) {
        int k = idx & 1023;
        int c = idx >> 10;
        w_s[c * W_LD + k] = gru_rk[(size_t)k * NG + (c >> 3) * NH + jb + (c & 7)];
    }
    const float brz = br[jb + j];
    const float brr = br[NH + jb + j];
    const float brh = br[2*NH + jb + j];
    __syncthreads();

    const int s_lane  = tid & 15;
    const int s_brow0 = tid >> 4;

    for (int t = 0; t < NT; t++) {
        u64 acc2[4][3];
#pragma unroll
        for (int i = 0; i < 4; i++)
#pragma unroll
            for (int g = 0; g < 3; g++) acc2[i][g] = 0ull;

        if (t > 0) {
            float4 pre[8];
            // stage tokens for this step
            if (tid < 128) tok_s[tid] = tokens[tid * NT + t];

            // prologue: chunk0 -> buf0, chunk1 -> pre
#pragma unroll
            for (int r = 0; r < 8; r++) {
                int bb = s_brow0 + 16 * r;
                pre[r] = __ldcg((const float4*)&g_hs[((size_t)bb * NT + (t-1)) * NH + s_lane * 4]);
            }
#pragma unroll
            for (int r = 0; r < 8; r++) {
                int bb = s_brow0 + 16 * r;
                *(float4*)&h_b[bb * H_LD + s_lane * 4] = pre[r];
            }
#pragma unroll
            for (int r = 0; r < 8; r++) {
                int bb = s_brow0 + 16 * r;
                pre[r] = __ldcg((const float4*)&g_hs[((size_t)bb * NT + (t-1)) * NH + KC + s_lane * 4]);
            }

            for (int c = 0; c < NH / KC; c++) {
                __syncthreads();
                // store chunk c+1 (in pre) into buf (c+1)&1; prefetch chunk c+2
                if (c + 1 < NH / KC) {
                    float* nb = h_b + ((c + 1) & 1) * HBUF_FLOATS;
#pragma unroll
                    for (int r = 0; r < 8; r++) {
                        int bb = s_brow0 + 16 * r;
                        *(float4*)&nb[bb * H_LD + s_lane * 4] = pre[r];
                    }
                    if (c + 2 < NH / KC) {
#pragma unroll
                        for (int r = 0; r < 8; r++) {
                            int bb = s_brow0 + 16 * r;
                            pre[r] = __ldcg((const float4*)&g_hs[((size_t)bb * NT + (t-1)) * NH
                                                                 + (c+2) * KC + s_lane * 4]);
                        }
                    }
                }
                // compute chunk c from buf c&1
                const float* hb = h_b + (c & 1) * HBUF_FLOATS;
                const int kg = c * KC;
#pragma unroll 4
                for (int kk = 0; kk < KC; kk += 2) {
                    u64 w0 = *(const u64*)&w_s[(0*8 + j) * W_LD + kg + kk];
                    u64 w1 = *(const u64*)&w_s[(1*8 + j) * W_LD + kg + kk];
                    u64 w2 = *(const u64*)&w_s[(2*8 + j) * W_LD + kg + kk];
#pragma unroll
                    for (int i = 0; i < 4; i++) {
                        u64 h2 = *(const u64*)&hb[(rg4 + 32*i) * H_LD + kk];
                        ffma2(acc2[i][0], h2, w0);
                        ffma2(acc2[i][1], h2, w1);
                        ffma2(acc2[i][2], h2, w2);
                    }
                }
            }
        } else {
            if (tid < 128) tok_s[tid] = tokens[tid * NT + 0];
            __syncthreads();
        }

        // ---- gates + h_t
#pragma unroll
        for (int i = 0; i < 4; i++) {
            int b = rg4 + 32 * i;
            float rz = lo32(acc2[i][0]) + hi32(acc2[i][0]) + brz;
            float rr = lo32(acc2[i][1]) + hi32(acc2[i][1]) + brr;
            float rh = lo32(acc2[i][2]) + hi32(acc2[i][2]) + brh;
            int tok = tok_s[b];
            const float* tab = g_table + (size_t)tok * NG + jb + j;
            float xz = tab[0], xr = tab[NH], xh = tab[2*NH];
            float z  = fsigmoid(xz + rz);
            float r  = fsigmoid(xr + rr);
            float hh = ftanh(xh + r * rh);
            float hp = (t > 0) ? __ldcg(&g_hs[((size_t)b * NT + (t-1)) * NH + jb + j]) : 0.0f;
            g_hs[((size_t)b * NT + t) * NH + jb + j] = z * hp + (1.0f - z) * hh;
        }

        // ---- grid barrier
        __syncthreads();
        if (tid == 0) {
            __threadfence();
            atomicAdd(&g_barcnt, 1u);   // result unused -> RED
            const unsigned target = (unsigned)NBLK * (unsigned)(t + 1);
            volatile unsigned* p = &g_barcnt;
            while (*p < target) { }
        }
        __syncthreads();
    }
}

// ---------------- softmax -------------------------------------------------------
__global__ __launch_bounds__(256)
void softmax_rows(float* __restrict__ out)
{
    __shared__ float4 row[NV / 4];     // 2500 float4 = 40KB
    __shared__ float red[256];
    const int tid = threadIdx.x;
    const float4* lp = (const float4*)(g_logits + (size_t)blockIdx.x * NV);
    float4* op = (float4*)(out + (size_t)blockIdx.x * NV);

    float m = -1e30f;
    for (int v = tid; v < NV/4; v += 256) {
        float4 x = lp[v];
        row[v] = x;
        m = fmaxf(fmaxf(fmaxf(m, x.x), fmaxf(x.y, x.z)), x.w);
    }
    red[tid] = m; __syncthreads();
    for (int s = 128; s > 0; s >>= 1) {
        if (tid < s) red[tid] = fmaxf(red[tid], red[tid + s]);
        __syncthreads();
    }
    const float smax = red[0];
    __syncthreads();

    float sum = 0.0f;
    for (int v = tid; v < NV/4; v += 256) {
        float4 x = row[v];
        x.x = __expf((x.x - smax) * 50.0f);
        x.y = __expf((x.y - smax) * 50.0f);
        x.z = __expf((x.z - smax) * 50.0f);
        x.w = __expf((x.w - smax) * 50.0f);
        row[v] = x;
        sum += x.x + x.y + x.z + x.w;
    }
    red[tid] = sum; __syncthreads();
    for (int s = 128; s > 0; s >>= 1) {
        if (tid < s) red[tid] += red[tid + s];
        __syncthreads();
    }
    const float inv = 1.0f / red[0];
    for (int v = tid; v < NV/4; v += 256) {
        float4 x = row[v];
        x.x *= inv; x.y *= inv; x.z *= inv; x.w *= inv;
        op[v] = x;
    }
}

// ---------------- launch ----------------
extern "C" void kernel_launch(void* const* d_in, const int* in_sizes, int n_in,
                              void* d_out, int out_size)
{
    const int*   tokens = (const int*)  d_in[0];
    const float* emb    = (const float*)d_in[1];
    const float* gru_k  = (const float*)d_in[2];
    const float* gru_rk = (const float*)d_in[3];
    const float* gru_bi = (const float*)d_in[4];
    const float* gru_br = (const float*)d_in[5];
    const float* w1     = (const float*)d_in[6];
    const float* b1     = (const float*)d_in[7];
    const float* w2     = (const float*)d_in[8];
    const float* b2     = (const float*)d_in[9];
    float* out = (float*)d_out;

    float* tablep = nullptr; cudaGetSymbolAddress((void**)&tablep, g_table);
    float* hsp    = nullptr; cudaGetSymbolAddress((void**)&hsp,    g_hs);
    float* dp     = nullptr; cudaGetSymbolAddress((void**)&dp,     g_d);
    float* logp   = nullptr; cudaGetSymbolAddress((void**)&logp,   g_logits);

    static int smem_set = 0;
    if (!smem_set) {
        cudaFuncSetAttribute(gru_persist, cudaFuncAttributeMaxDynamicSharedMemorySize,
                             PERSIST_SMEM_BYTES);
        smem_set = 1;
    }

    // 1) table = emb @ gru_k + gru_bi   [NV, NG], K=NE
    {
        dim3 grid(NG/128, (NV + 127)/128);   // 24 x 79
        gemm_f32x2<<<grid, 256>>>(emb, NE, gru_k, NG, tablep, NG,
                                  NV, NG, NE, gru_bi, 0);
    }

    // 2) persistent GRU scan
    reset_bar<<<1, 1>>>();
    gru_persist<<<NBLK, 256, PERSIST_SMEM_BYTES>>>(tokens, gru_rk, gru_br);

    // 3) d = relu(hs @ w1 + b1)         [NB*NT, ND], K=NH
    {
        dim3 grid(1, (NB*NT)/128);           // 1 x 128
        gemm_f32x2<<<grid, 256>>>(hsp, NH, w1, ND, dp, ND,
                                  NB*NT, ND, NH, b1, 1);
    }

    // 4) logits = d @ w2 + b2           [NB*NT, NV], K=ND
    {
        dim3 grid((NV + 127)/128, (NB*NT)/128);   // 79 x 128
        gemm_f32x2<<<grid, 256>>>(dp, ND, w2, NV, logp, NV,
                                  NB*NT, NV, ND, b2, 0);
    }

    // 5) softmax
    softmax_rows<<<NB*NT, 256>>>(out);
}

// round 4
// speedup vs baseline: 1.6339x; 1.6339x over previous
#include <cuda_runtime.h>
#include <cuda_bf16.h>
#include <math.h>

#define NB 128
#define NT 128
#define NV 10000
#define NE 256
#define NH 1024
#define ND 128
#define NG 3072   // 3*NH

#define NBLK 128
#define KC   64
#define W_LD 1028
#define H_LD 68

typedef unsigned long long u64;
typedef __nv_bfloat16 bf16;

// ---------------- scratch ----------------
__device__ float g_table[(size_t)NV * NG];
__device__ float g_hs[(size_t)NB * NT * NH];
__device__ float g_logits[(size_t)NB * NT * NV];
__device__ unsigned g_barcnt;
// split operands (bf16, K-concat [hi|hi|lo] for A-side, [hi|lo|hi] rows for Bt-side)
__device__ bf16 g_embs[(size_t)NV * (3*NE)];          // [10000][768]
__device__ bf16 g_gukt[(size_t)NG * (3*NE)];          // [3072][768]
__device__ bf16 g_hss [(size_t)NB*NT * (3*NH)];       // [16384][3072]
__device__ bf16 g_w1t [(size_t)ND * (3*NH)];          // [128][3072]
__device__ bf16 g_ds  [(size_t)NB*NT * (3*ND)];       // [16384][384]
__device__ bf16 g_w2t [(size_t)NV * (3*ND)];          // [10000][384]

__device__ __forceinline__ void ffma2(u64& d, u64 a, u64 b) {
    asm("fma.rn.f32x2 %0, %1, %2, %0;" : "+l"(d) : "l"(a), "l"(b));
}
__device__ __forceinline__ float lo32(u64 v) { return __uint_as_float((unsigned)v); }
__device__ __forceinline__ float hi32(u64 v) { return __uint_as_float((unsigned)(v >> 32)); }

// ================= split/transpose prep kernels =================
// A-side: dst[m][0:K)=hi, [K:2K)=hi, [2K:3K)=lo
__global__ __launch_bounds__(256)
void split_rows(const float* __restrict__ src, int M, int K, bf16* __restrict__ dst)
{
    size_t idx = (size_t)blockIdx.x * 256 + threadIdx.x;
    if (idx >= (size_t)M * K) return;
    int m = (int)(idx / K), k = (int)(idx % K);
    float x = src[idx];
    bf16 h = __float2bfloat16(x);
    bf16 l = __float2bfloat16(x - __bfloat162float(h));
    bf16* d = dst + (size_t)m * 3 * K;
    d[k] = h; d[K + k] = h; d[2*K + k] = l;
}

// B-side: src [K][N] -> dst [N][3K], rows [0:K)=hi, [K:2K)=lo, [2K:3K)=hi
__global__ __launch_bounds__(256)
void transp_split(const float* __restrict__ src, int K, int N, bf16* __restrict__ dst)
{
    __shared__ float tile[32][33];
    int k0 = blockIdx.y * 32, n0 = blockIdx.x * 32;
    int tx = threadIdx.x & 31, ty = threadIdx.x >> 5;   // 256 thr: ty 0..7
    for (int i = ty; i < 32; i += 8) {
        int k = k0 + i, n = n0 + tx;
        tile[i][tx] = (k < K && n < N) ? src[(size_t)k * N + n] : 0.0f;
    }
    __syncthreads();
    for (int i = ty; i < 32; i += 8) {
        int n = n0 + i, k = k0 + tx;
        if (n < N && k < K) {
            float x = tile[tx][i];
            bf16 h = __float2bfloat16(x);
            bf16 l = __float2bfloat16(x - __bfloat162float(h));
            bf16* d = dst + (size_t)n * 3 * K;
            d[k] = h; d[K + k] = l; d[2*K + k] = h;
        }
    }
}

// ================= bf16 tensor-core GEMM =================
// C[M,N] = A'[M,K3] @ Bt'[N,K3]^T  (split operands already K-concatenated)
// block 128x128, BK=32, 8 warps (2m x 4n), warp tile 64x32, mma m16n8k16.
#define GSTR 40   // smem row stride in bf16 (conflict-free)

__global__ __launch_bounds__(256)
void gemm_bf16s(const bf16* __restrict__ A, int lda,
                const bf16* __restrict__ Bt, int ldb,
                int M, int N, int K3,
                const float* __restrict__ bias, int relu,
                float* __restrict__ C, int ldc,
                bf16* __restrict__ Cs, int Kout)   // optional split A'-layout out
{
    __shared__ bf16 As[128 * GSTR];
    __shared__ bf16 Bs[128 * GSTR];

    const int tid  = threadIdx.x;
    const int lane = tid & 31;
    const int warp = tid >> 5;
    const int bm0 = blockIdx.y * 128, bn0 = blockIdx.x * 128;
    const int wm0 = (warp >> 2) * 64, wn0 = (warp & 3) * 32;

    float c[4][4][4];
#pragma unroll
    for (int mi = 0; mi < 4; mi++)
#pragma unroll
        for (int ni = 0; ni < 4; ni++)
#pragma unroll
            for (int q = 0; q < 4; q++) c[mi][ni][q] = 0.0f;

    for (int k0 = 0; k0 < K3; k0 += 32) {
        // load A tile 128x32
#pragma unroll
        for (int it = 0; it < 2; it++) {
            int idx = tid + 256 * it;
            int r = idx >> 2, seg = (idx & 3) * 8;
            int gm = bm0 + r; if (gm > M-1) gm = M-1;
            uint4 v = *(const uint4*)&A[(size_t)gm * lda + k0 + seg];
            *(uint4*)&As[r * GSTR + seg] = v;
        }
        // load B tile (rows = n) 128x32
#pragma unroll
        for (int it = 0; it < 2; it++) {
            int idx = tid + 256 * it;
            int r = idx >> 2, seg = (idx & 3) * 8;
            int gn = bn0 + r; if (gn > N-1) gn = N-1;
            uint4 v = *(const uint4*)&Bt[(size_t)gn * ldb + k0 + seg];
            *(uint4*)&Bs[r * GSTR + seg] = v;
        }
        __syncthreads();

#pragma unroll
        for (int ks = 0; ks < 2; ks++) {
            unsigned bfr[4][2];
#pragma unroll
            for (int ni = 0; ni < 4; ni++) {
                const bf16* p = &Bs[(wn0 + ni*8 + (lane >> 2)) * GSTR + ks*16 + (lane & 3)*2];
                bfr[ni][0] = *(const unsigned*)p;
                bfr[ni][1] = *(const unsigned*)(p + 8);
            }
#pragma unroll
            for (int mi = 0; mi < 4; mi++) {
                unsigned a0, a1, a2, a3;
                unsigned saddr = (unsigned)__cvta_generic_to_shared(
                    &As[(wm0 + mi*16 + (lane & 15)) * GSTR + ks*16 + (lane >> 4)*8]);
                asm volatile("ldmatrix.sync.aligned.m8n8.x4.shared.b16 {%0,%1,%2,%3},[%4];"
                             : "=r"(a0), "=r"(a1), "=r"(a2), "=r"(a3) : "r"(saddr));
#pragma unroll
                for (int ni = 0; ni < 4; ni++) {
                    asm volatile(
                        "mma.sync.aligned.m16n8k16.row.col.f32.bf16.bf16.f32 "
                        "{%0,%1,%2,%3},{%4,%5,%6,%7},{%8,%9},{%0,%1,%2,%3};"
                        : "+f"(c[mi][ni][0]), "+f"(c[mi][ni][1]),
                          "+f"(c[mi][ni][2]), "+f"(c[mi][ni][3])
                        : "r"(a0), "r"(a1), "r"(a2), "r"(a3),
                          "r"(bfr[ni][0]), "r"(bfr[ni][1]));
                }
            }
        }
        __syncthreads();
    }

    // epilogue
#pragma unroll
    for (int mi = 0; mi < 4; mi++) {
#pragma unroll
        for (int ni = 0; ni < 4; ni++) {
            int r0  = bm0 + wm0 + mi*16 + (lane >> 2);
            int col = bn0 + wn0 + ni*8 + (lane & 3)*2;
#pragma unroll
            for (int q = 0; q < 4; q++) {
                int gm = r0 + (q >> 1) * 8;
                int gn = col + (q & 1);
                if (gm >= M || gn >= N) continue;
                float v = c[mi][ni][q];
                if (bias) v += bias[gn];
                if (relu) v = fmaxf(v, 0.0f);
                if (C) C[(size_t)gm * ldc + gn] = v;
                if (Cs) {
                    bf16 h = __float2bfloat16(v);
                    bf16 l = __float2bfloat16(v - __bfloat162float(h));
                    bf16* d = Cs + (size_t)gm * 3 * Kout;
                    d[gn] = h; d[Kout + gn] = h; d[2*Kout + gn] = l;
                }
            }
        }
    }
}

// ================= persistent GRU (R2 verbatim) =================
__global__ void reset_bar() { g_barcnt = 0u; }

#define W_FLOATS (24 * W_LD)
#define HBUF_FLOATS (128 * H_LD)
#define PERSIST_SMEM_BYTES ((W_FLOATS + 2 * HBUF_FLOATS) * 4)

__global__ __launch_bounds__(256, 1)
void gru_persist(const int* __restrict__ tokens,
                 const float* __restrict__ gru_rk,
                 const float* __restrict__ br)
{
    extern __shared__ float sm[];
    float* w_s = sm;
    float* h_b = sm + W_FLOATS;

    const int tid = threadIdx.x;
    const int bid = blockIdx.x;
    const int j   = tid & 7;
    const int rg4 = tid >> 3;
    const int jb  = bid * 8;

    for (int idx = tid; idx < 1024 * 24; idx += 256) {
        int k = idx & 1023;
        int c = idx >> 10;
        w_s[c * W_LD + k] = gru_rk[(size_t)k * NG + (c >> 3) * NH + jb + (c & 7)];
    }
    const float brz = br[jb + j];
    const float brr = br[NH + jb + j];
    const float brh = br[2*NH + jb + j];
    __syncthreads();

    const int s_lane  = tid & 15;
    const int s_brow0 = tid >> 4;

    for (int t = 0; t < NT; t++) {
        u64 acc2[4][3];
#pragma unroll
        for (int i = 0; i < 4; i++)
#pragma unroll
            for (int g = 0; g < 3; g++) acc2[i][g] = 0ull;

        if (t > 0) {
            float4 pre[8];
#pragma unroll
            for (int r = 0; r < 8; r++) {
                int bb = s_brow0 + 16 * r;
                pre[r] = __ldcg((const float4*)&g_hs[((size_t)bb * NT + (t-1)) * NH + s_lane * 4]);
            }
#pragma unroll
            for (int r = 0; r < 8; r++) {
                int bb = s_brow0 + 16 * r;
                *(float4*)&h_b[bb * H_LD + s_lane * 4] = pre[r];
            }
            __syncthreads();

            for (int c = 0; c < NH / KC; c++) {
                if (c + 1 < NH / KC) {
#pragma unroll
                    for (int r = 0; r < 8; r++) {
                        int bb = s_brow0 + 16 * r;
                        pre[r] = __ldcg((const float4*)&g_hs[((size_t)bb * NT + (t-1)) * NH
                                                             + (c+1) * KC + s_lane * 4]);
                    }
                }
                const float* hb = h_b + (c & 1) * HBUF_FLOATS;
                const int kg = c * KC;
#pragma unroll 4
                for (int kk = 0; kk < KC; kk += 2) {
                    u64 w0 = *(const u64*)&w_s[(0*8 + j) * W_LD + kg + kk];
                    u64 w1 = *(const u64*)&w_s[(1*8 + j) * W_LD + kg + kk];
                    u64 w2 = *(const u64*)&w_s[(2*8 + j) * W_LD + kg + kk];
#pragma unroll
                    for (int i = 0; i < 4; i++) {
                        u64 h2 = *(const u64*)&hb[(rg4 + 32*i) * H_LD + kk];
                        ffma2(acc2[i][0], h2, w0);
                        ffma2(acc2[i][1], h2, w1);
                        ffma2(acc2[i][2], h2, w2);
                    }
                }
                __syncthreads();
                if (c + 1 < NH / KC) {
                    float* nb = h_b + ((c + 1) & 1) * HBUF_FLOATS;
#pragma unroll
                    for (int r = 0; r < 8; r++) {
                        int bb = s_brow0 + 16 * r;
                        *(float4*)&nb[bb * H_LD + s_lane * 4] = pre[r];
                    }
                    __syncthreads();
                }
            }
        }

#pragma unroll
        for (int i = 0; i < 4; i++) {
            int b = rg4 + 32 * i;
            float rz = lo32(acc2[i][0]) + hi32(acc2[i][0]) + brz;
            float rr = lo32(acc2[i][1]) + hi32(acc2[i][1]) + brr;
            float rh = lo32(acc2[i][2]) + hi32(acc2[i][2]) + brh;
            int tok = tokens[b * NT + t];
            const float* tab = g_table + (size_t)tok * NG + jb + j;
            float xz = tab[0], xr = tab[NH], xh = tab[2*NH];
            float z  = 1.0f / (1.0f + expf(-(xz + rz)));
            float r  = 1.0f / (1.0f + expf(-(xr + rr)));
            float hh = tanhf(xh + r * rh);
            float hp = (t > 0) ? __ldcg(&g_hs[((size_t)b * NT + (t-1)) * NH + jb + j]) : 0.0f;
            g_hs[((size_t)b * NT + t) * NH + jb + j] = z * hp + (1.0f - z) * hh;
        }

        __syncthreads();
        if (tid == 0) {
            __threadfence();
            atomicAdd(&g_barcnt, 1u);
            const unsigned target = (unsigned)NBLK * (unsigned)(t + 1);
            while (atomicAdd(&g_barcnt, 0u) < target) { }
        }
        __syncthreads();
    }
}

// ================= softmax (R2 verbatim) =================
__global__ __launch_bounds__(256)
void softmax_rows(float* __restrict__ out)
{
    __shared__ float row[NV];
    __shared__ float red[256];
    const int tid = threadIdx.x;
    const size_t r0 = (size_t)blockIdx.x * NV;

    float m = -1e30f;
    for (int v = tid; v < NV; v += 256) {
        float x = g_logits[r0 + v];
        row[v] = x;
        m = fmaxf(m, x);
    }
    red[tid] = m; __syncthreads();
    for (int s = 128; s > 0; s >>= 1) {
        if (tid < s) red[tid] = fmaxf(red[tid], red[tid + s]);
        __syncthreads();
    }
    const float smax = red[0];
    __syncthreads();

    float sum = 0.0f;
    for (int v = tid; v < NV; v += 256) {
        float e = expf((row[v] - smax) * 50.0f);
        row[v] = e;
        sum += e;
    }
    red[tid] = sum; __syncthreads();
    for (int s = 128; s > 0; s >>= 1) {
        if (tid < s) red[tid] += red[tid + s];
        __syncthreads();
    }
    const float inv = 1.0f / red[0];
    for (int v = tid; v < NV; v += 256)
        out[r0 + v] = row[v] * inv;
}

// ================= launch =================
extern "C" void kernel_launch(void* const* d_in, const int* in_sizes, int n_in,
                              void* d_out, int out_size)
{
    const int*   tokens = (const int*)  d_in[0];
    const float* emb    = (const float*)d_in[1];
    const float* gru_k  = (const float*)d_in[2];
    const float* gru_rk = (const float*)d_in[3];
    const float* gru_bi = (const float*)d_in[4];
    const float* gru_br = (const float*)d_in[5];
    const float* w1     = (const float*)d_in[6];
    const float* b1     = (const float*)d_in[7];
    const float* w2     = (const float*)d_in[8];
    const float* b2     = (const float*)d_in[9];
    float* out = (float*)d_out;

    float* tablep = nullptr; cudaGetSymbolAddress((void**)&tablep, g_table);
    float* hsp    = nullptr; cudaGetSymbolAddress((void**)&hsp,    g_hs);
    float* logp   = nullptr; cudaGetSymbolAddress((void**)&logp,   g_logits);
    bf16* embs = nullptr; cudaGetSymbolAddress((void**)&embs, g_embs);
    bf16* gukt = nullptr; cudaGetSymbolAddress((void**)&gukt, g_gukt);
    bf16* hss  = nullptr; cudaGetSymbolAddress((void**)&hss,  g_hss);
    bf16* w1t  = nullptr; cudaGetSymbolAddress((void**)&w1t,  g_w1t);
    bf16* ds   = nullptr; cudaGetSymbolAddress((void**)&ds,   g_ds);
    bf16* w2t  = nullptr; cudaGetSymbolAddress((void**)&w2t,  g_w2t);

    static int smem_set = 0;
    if (!smem_set) {
        cudaFuncSetAttribute(gru_persist, cudaFuncAttributeMaxDynamicSharedMemorySize,
                             PERSIST_SMEM_BYTES);
        smem_set = 1;
    }

    // 0) split/transpose prep
    split_rows<<<(NV*NE + 255)/256, 256>>>(emb, NV, NE, embs);
    { dim3 g((NG+31)/32, (NE+31)/32);  transp_split<<<g, 256>>>(gru_k, NE, NG, gukt); }
    { dim3 g((ND+31)/32, (NH+31)/32);  transp_split<<<g, 256>>>(w1, NH, ND, w1t); }
    { dim3 g((NV+31)/32, (ND+31)/32);  transp_split<<<g, 256>>>(w2, ND, NV, w2t); }

    // 1) table = emb @ gru_k + gru_bi   [NV, NG]
    {
        dim3 grid(NG/128, (NV + 127)/128);   // 24 x 79
        gemm_bf16s<<<grid, 256>>>(embs, 3*NE, gukt, 3*NE, NV, NG, 3*NE,
                                  gru_bi, 0, tablep, NG, nullptr, 0);
    }

    // 2) persistent GRU scan
    reset_bar<<<1, 1>>>();
    gru_persist<<<NBLK, 256, PERSIST_SMEM_BYTES>>>(tokens, gru_rk, gru_br);

    // 2.5) split hs
    split_rows<<<(NB*NT*NH + 255)/256, 256>>>(hsp, NB*NT, NH, hss);

    // 3) d' = split(relu(hs @ w1 + b1))  [16384, 384]
    {
        dim3 grid(1, (NB*NT)/128);
        gemm_bf16s<<<grid, 256>>>(hss, 3*NH, w1t, 3*NH, NB*NT, ND, 3*NH,
                                  b1, 1, nullptr, 0, ds, ND);
    }

    // 4) logits = d @ w2 + b2           [16384, NV]
    {
        dim3 grid((NV + 127)/128, (NB*NT)/128);
        gemm_bf16s<<<grid, 256>>>(ds, 3*ND, w2t, 3*ND, NB*NT, NV, 3*ND,
                                  b2, 0, logp, NV, nullptr, 0);
    }

    // 5) softmax
    softmax_rows<<<NB*NT, 256>>>(out);
}

// round 5
// speedup vs baseline: 2.2786x; 1.3945x over previous
#include <cuda_runtime.h>
#include <cuda_bf16.h>
#include <math.h>

#define NB 128
#define NT 128
#define NV 10000
#define NE 256
#define NH 1024
#define ND 128
#define NG 3072   // 3*NH

#define NBLK 128

typedef unsigned long long u64;
typedef __nv_bfloat16 bf16;

// ---------------- scratch ----------------
__device__ float g_table[(size_t)NV * NG];
__device__ float g_hs[(size_t)NB * NT * NH];
__device__ float g_logits[(size_t)NB * NT * NV];
__device__ unsigned g_barcnt;
__device__ bf16 g_hsplit[2][(size_t)NB * 2048];       // [parity][b][hi(1024)|lo(1024)]
// split operands for head GEMMs
__device__ bf16 g_embs[(size_t)NV * (3*NE)];
__device__ bf16 g_gukt[(size_t)NG * (3*NE)];
__device__ bf16 g_hss [(size_t)NB*NT * (3*NH)];
__device__ bf16 g_w1t [(size_t)ND * (3*NH)];
__device__ bf16 g_ds  [(size_t)NB*NT * (3*ND)];
__device__ bf16 g_w2t [(size_t)NV * (3*ND)];

// ================= split/transpose prep (R4 verbatim) =================
__global__ __launch_bounds__(256)
void split_rows(const float* __restrict__ src, int M, int K, bf16* __restrict__ dst)
{
    size_t idx = (size_t)blockIdx.x * 256 + threadIdx.x;
    if (idx >= (size_t)M * K) return;
    int m = (int)(idx / K), k = (int)(idx % K);
    float x = src[idx];
    bf16 h = __float2bfloat16(x);
    bf16 l = __float2bfloat16(x - __bfloat162float(h));
    bf16* d = dst + (size_t)m * 3 * K;
    d[k] = h; d[K + k] = h; d[2*K + k] = l;
}

__global__ __launch_bounds__(256)
void transp_split(const float* __restrict__ src, int K, int N, bf16* __restrict__ dst)
{
    __shared__ float tile[32][33];
    int k0 = blockIdx.y * 32, n0 = blockIdx.x * 32;
    int tx = threadIdx.x & 31, ty = threadIdx.x >> 5;
    for (int i = ty; i < 32; i += 8) {
        int k = k0 + i, n = n0 + tx;
        tile[i][tx] = (k < K && n < N) ? src[(size_t)k * N + n] : 0.0f;
    }
    __syncthreads();
    for (int i = ty; i < 32; i += 8) {
        int n = n0 + i, k = k0 + tx;
        if (n < N && k < K) {
            float x = tile[tx][i];
            bf16 h = __float2bfloat16(x);
            bf16 l = __float2bfloat16(x - __bfloat162float(h));
            bf16* d = dst + (size_t)n * 3 * K;
            d[k] = h; d[K + k] = l; d[2*K + k] = h;
        }
    }
}

// ================= bf16 tensor-core GEMM (R4 verbatim) =================
#define GSTR 40

__global__ __launch_bounds__(256)
void gemm_bf16s(const bf16* __restrict__ A, int lda,
                const bf16* __restrict__ Bt, int ldb,
                int M, int N, int K3,
                const float* __restrict__ bias, int relu,
                float* __restrict__ C, int ldc,
                bf16* __restrict__ Cs, int Kout)
{
    __shared__ bf16 As[128 * GSTR];
    __shared__ bf16 Bs[128 * GSTR];

    const int tid  = threadIdx.x;
    const int lane = tid & 31;
    const int warp = tid >> 5;
    const int bm0 = blockIdx.y * 128, bn0 = blockIdx.x * 128;
    const int wm0 = (warp >> 2) * 64, wn0 = (warp & 3) * 32;

    float c[4][4][4];
#pragma unroll
    for (int mi = 0; mi < 4; mi++)
#pragma unroll
        for (int ni = 0; ni < 4; ni++)
#pragma unroll
            for (int q = 0; q < 4; q++) c[mi][ni][q] = 0.0f;

    for (int k0 = 0; k0 < K3; k0 += 32) {
#pragma unroll
        for (int it = 0; it < 2; it++) {
            int idx = tid + 256 * it;
            int r = idx >> 2, seg = (idx & 3) * 8;
            int gm = bm0 + r; if (gm > M-1) gm = M-1;
            uint4 v = *(const uint4*)&A[(size_t)gm * lda + k0 + seg];
            *(uint4*)&As[r * GSTR + seg] = v;
        }
#pragma unroll
        for (int it = 0; it < 2; it++) {
            int idx = tid + 256 * it;
            int r = idx >> 2, seg = (idx & 3) * 8;
            int gn = bn0 + r; if (gn > N-1) gn = N-1;
            uint4 v = *(const uint4*)&Bt[(size_t)gn * ldb + k0 + seg];
            *(uint4*)&Bs[r * GSTR + seg] = v;
        }
        __syncthreads();

#pragma unroll
        for (int ks = 0; ks < 2; ks++) {
            unsigned bfr[4][2];
#pragma unroll
            for (int ni = 0; ni < 4; ni++) {
                const bf16* p = &Bs[(wn0 + ni*8 + (lane >> 2)) * GSTR + ks*16 + (lane & 3)*2];
                bfr[ni][0] = *(const unsigned*)p;
                bfr[ni][1] = *(const unsigned*)(p + 8);
            }
#pragma unroll
            for (int mi = 0; mi < 4; mi++) {
                unsigned a0, a1, a2, a3;
                unsigned saddr = (unsigned)__cvta_generic_to_shared(
                    &As[(wm0 + mi*16 + (lane & 15)) * GSTR + ks*16 + (lane >> 4)*8]);
                asm volatile("ldmatrix.sync.aligned.m8n8.x4.shared.b16 {%0,%1,%2,%3},[%4];"
                             : "=r"(a0), "=r"(a1), "=r"(a2), "=r"(a3) : "r"(saddr));
#pragma unroll
                for (int ni = 0; ni < 4; ni++) {
                    asm volatile(
                        "mma.sync.aligned.m16n8k16.row.col.f32.bf16.bf16.f32 "
                        "{%0,%1,%2,%3},{%4,%5,%6,%7},{%8,%9},{%0,%1,%2,%3};"
                        : "+f"(c[mi][ni][0]), "+f"(c[mi][ni][1]),
                          "+f"(c[mi][ni][2]), "+f"(c[mi][ni][3])
                        : "r"(a0), "r"(a1), "r"(a2), "r"(a3),
                          "r"(bfr[ni][0]), "r"(bfr[ni][1]));
                }
            }
        }
        __syncthreads();
    }

#pragma unroll
    for (int mi = 0; mi < 4; mi++) {
#pragma unroll
        for (int ni = 0; ni < 4; ni++) {
            int r0  = bm0 + wm0 + mi*16 + (lane >> 2);
            int col = bn0 + wn0 + ni*8 + (lane & 3)*2;
#pragma unroll
            for (int q = 0; q < 4; q++) {
                int gm = r0 + (q >> 1) * 8;
                int gn = col + (q & 1);
                if (gm >= M || gn >= N) continue;
                float v = c[mi][ni][q];
                if (bias) v += bias[gn];
                if (relu) v = fmaxf(v, 0.0f);
                if (C) C[(size_t)gm * ldc + gn] = v;
                if (Cs) {
                    bf16 h = __float2bfloat16(v);
                    bf16 l = __float2bfloat16(v - __bfloat162float(h));
                    bf16* d = Cs + (size_t)gm * 3 * Kout;
                    d[gn] = h; d[Kout + gn] = h; d[2*Kout + gn] = l;
                }
            }
        }
    }
}

// ================= tensor-core persistent GRU =================
__global__ void reset_bar() { g_barcnt = 0u; }

#define W_STR 2056                  // bf16 stride of w_s rows
#define A_LD  136                   // bf16 stride of staged h rows
#define KCH   128                   // h cols per staged chunk
#define NCHUNK 16                   // 2048 / KCH
#define GRU_SMEM_BYTES ((24*W_STR + 2*128*A_LD) * 2 + 128*4 + 16)

__global__ __launch_bounds__(256, 1)
void gru_persist_tc(const int* __restrict__ tokens,
                    const float* __restrict__ gru_rk,
                    const float* __restrict__ br)
{
    extern __shared__ char smc[];
    bf16* w_s   = (bf16*)smc;                         // [24][W_STR]: [w_hi(1024)|w_lo(1024)]
    bf16* As    = w_s + 24 * W_STR;                   // 2 x [128][A_LD]
    int*  tok_s = (int*)(As + 2 * 128 * A_LD);        // [128]

    const int tid  = threadIdx.x;
    const int bid  = blockIdx.x;
    const int lane = tid & 31;
    const int warp = tid >> 5;
    const int jb   = bid * 8;
    const int m0   = warp * 16;

    // resident split weights: w_s[c][k] : c = gate*8 + jcol
    for (int idx = tid; idx < 24 * 2048; idx += 256) {
        int c = idx >> 11, k = idx & 2047;
        int kk = k & 1023;
        float v = gru_rk[(size_t)kk * NG + (c >> 3) * NH + jb + (c & 7)];
        bf16 h = __float2bfloat16(v);
        w_s[c * W_STR + k] = (k < 1024) ? h : __float2bfloat16(v - __bfloat162float(h));
    }
    const int j0 = (lane & 3) * 2;
    const float brz0 = br[jb + j0],        brz1 = br[jb + j0 + 1];
    const float brr0 = br[NH + jb + j0],   brr1 = br[NH + jb + j0 + 1];
    const float brh0 = br[2*NH + jb + j0], brh1 = br[2*NH + jb + j0 + 1];
    __syncthreads();

    const int s_row = tid >> 4;       // 0..15
    const int s_seg = tid & 15;       // 16B segment within 256B row-chunk

    for (int t = 0; t < NT; t++) {
        float acc[3][4];
#pragma unroll
        for (int g = 0; g < 3; g++)
#pragma unroll
            for (int q = 0; q < 4; q++) acc[g][q] = 0.0f;

        if (tid < 128) tok_s[tid] = tokens[tid * NT + t];

        if (t > 0) {
            const bf16* hsrc = g_hsplit[(t + 1) & 1];

            // stage chunk 0
#pragma unroll
            for (int i = 0; i < 8; i++) {
                int row = s_row + 16 * i;
                uint4 v = __ldcg((const uint4*)&hsrc[(size_t)row * 2048] + s_seg);
                *(uint4*)&As[row * A_LD + s_seg * 8] = v;
            }
            __syncthreads();

            for (int c = 0; c < NCHUNK; c++) {
                if (c + 1 < NCHUNK) {
                    bf16* dst = As + ((c + 1) & 1) * 128 * A_LD;
#pragma unroll
                    for (int i = 0; i < 8; i++) {
                        int row = s_row + 16 * i;
                        uint4 v = __ldcg((const uint4*)&hsrc[(size_t)row * 2048 + (c+1) * KCH] + s_seg);
                        *(uint4*)&dst[row * A_LD + s_seg * 8] = v;
                    }
                }
                const bf16* ab = As + (c & 1) * 128 * A_LD;
                const bool hi = (c < 8);
                const int kbase = hi ? c * KCH : (c - 8) * KCH;
#pragma unroll
                for (int ks = 0; ks < KCH / 16; ks++) {
                    unsigned a0, a1, a2, a3;
                    unsigned sa = (unsigned)__cvta_generic_to_shared(
                        &ab[(m0 + (lane & 15)) * A_LD + ks * 16 + (lane >> 4) * 8]);
                    asm volatile("ldmatrix.sync.aligned.m8n8.x4.shared.b16 {%0,%1,%2,%3},[%4];"
                                 : "=r"(a0), "=r"(a1), "=r"(a2), "=r"(a3) : "r"(sa));
                    const int kg = kbase + ks * 16;
                    // h_chunk . w_hi  (all 3 gates)
#pragma unroll
                    for (int g = 0; g < 3; g++) {
                        const bf16* p = &w_s[(g*8 + (lane >> 2)) * W_STR + kg + (lane & 3)*2];
                        unsigned b0 = *(const unsigned*)p;
                        unsigned b1 = *(const unsigned*)(p + 8);
                        asm volatile(
                            "mma.sync.aligned.m16n8k16.row.col.f32.bf16.bf16.f32 "
                            "{%0,%1,%2,%3},{%4,%5,%6,%7},{%8,%9},{%0,%1,%2,%3};"
                            : "+f"(acc[g][0]), "+f"(acc[g][1]), "+f"(acc[g][2]), "+f"(acc[g][3])
                            : "r"(a0), "r"(a1), "r"(a2), "r"(a3), "r"(b0), "r"(b1));
                    }
                    if (hi) {
                        // h_hi . w_lo  (reuse A frag)
#pragma unroll
                        for (int g = 0; g < 3; g++) {
                            const bf16* p = &w_s[(g*8 + (lane >> 2)) * W_STR + 1024 + kg + (lane & 3)*2];
                            unsigned b0 = *(const unsigned*)p;
                            unsigned b1 = *(const unsigned*)(p + 8);
                            asm volatile(
                                "mma.sync.aligned.m16n8k16.row.col.f32.bf16.bf16.f32 "
                                "{%0,%1,%2,%3},{%4,%5,%6,%7},{%8,%9},{%0,%1,%2,%3};"
                                : "+f"(acc[g][0]), "+f"(acc[g][1]), "+f"(acc[g][2]), "+f"(acc[g][3])
                                : "r"(a0), "r"(a1), "r"(a2), "r"(a3), "r"(b0), "r"(b1));
                        }
                    }
                }
                __syncthreads();
            }
        } else {
            __syncthreads();
        }

        // ---- gates: lane owns rows m0+(lane>>2)+{0,8}, cols jb+j0, jb+j0+1
        bf16* hout = g_hsplit[t & 1];
#pragma unroll
        for (int rr = 0; rr < 2; rr++) {
            int b = m0 + (lane >> 2) + rr * 8;
            int tok = tok_s[b];
            const float* tab = g_table + (size_t)tok * NG + jb;
            float h2[2];
#pragma unroll
            for (int qq = 0; qq < 2; qq++) {
                int j = j0 + qq;
                float rz = acc[0][rr*2 + qq] + (qq ? brz1 : brz0);
                float rrg= acc[1][rr*2 + qq] + (qq ? brr1 : brr0);
                float rh = acc[2][rr*2 + qq] + (qq ? brh1 : brh0);
                float xz = tab[j], xr = tab[NH + j], xh = tab[2*NH + j];
                float z  = 1.0f / (1.0f + expf(-(xz + rz)));
                float r  = 1.0f / (1.0f + expf(-(xr + rrg)));
                float hh = tanhf(xh + r * rh);
                float hp = (t > 0) ? g_hs[((size_t)b * NT + (t-1)) * NH + jb + j] : 0.0f;
                h2[qq] = z * hp + (1.0f - z) * hh;
            }
            *(float2*)&g_hs[((size_t)b * NT + t) * NH + jb + j0] = make_float2(h2[0], h2[1]);
            bf16 h0h = __float2bfloat16(h2[0]);
            bf16 h1h = __float2bfloat16(h2[1]);
            bf16 h0l = __float2bfloat16(h2[0] - __bfloat162float(h0h));
            bf16 h1l = __float2bfloat16(h2[1] - __bfloat162float(h1h));
            __nv_bfloat162 ph; ph.x = h0h; ph.y = h1h;
            __nv_bfloat162 pl; pl.x = h0l; pl.y = h1l;
            *(__nv_bfloat162*)&hout[(size_t)b * 2048 + jb + j0]        = ph;
            *(__nv_bfloat162*)&hout[(size_t)b * 2048 + 1024 + jb + j0] = pl;
        }

        // ---- grid barrier (R2 verbatim)
        __syncthreads();
        if (tid == 0) {
            __threadfence();
            atomicAdd(&g_barcnt, 1u);
            const unsigned target = (unsigned)NBLK * (unsigned)(t + 1);
            while (atomicAdd(&g_barcnt, 0u) < target) { }
        }
        __syncthreads();
    }
}

// ================= softmax (R2 verbatim) =================
__global__ __launch_bounds__(256)
void softmax_rows(float* __restrict__ out)
{
    __shared__ float row[NV];
    __shared__ float red[256];
    const int tid = threadIdx.x;
    const size_t r0 = (size_t)blockIdx.x * NV;

    float m = -1e30f;
    for (int v = tid; v < NV; v += 256) {
        float x = g_logits[r0 + v];
        row[v] = x;
        m = fmaxf(m, x);
    }
    red[tid] = m; __syncthreads();
    for (int s = 128; s > 0; s >>= 1) {
        if (tid < s) red[tid] = fmaxf(red[tid], red[tid + s]);
        __syncthreads();
    }
    const float smax = red[0];
    __syncthreads();

    float sum = 0.0f;
    for (int v = tid; v < NV; v += 256) {
        float e = expf((row[v] - smax) * 50.0f);
        row[v] = e;
        sum += e;
    }
    red[tid] = sum; __syncthreads();
    for (int s = 128; s > 0; s >>= 1) {
        if (tid < s) red[tid] += red[tid + s];
        __syncthreads();
    }
    const float inv = 1.0f / red[0];
    for (int v = tid; v < NV; v += 256)
        out[r0 + v] = row[v] * inv;
}

// ================= launch =================
extern "C" void kernel_launch(void* const* d_in, const int* in_sizes, int n_in,
                              void* d_out, int out_size)
{
    const int*   tokens = (const int*)  d_in[0];
    const float* emb    = (const float*)d_in[1];
    const float* gru_k  = (const float*)d_in[2];
    const float* gru_rk = (const float*)d_in[3];
    const float* gru_bi = (const float*)d_in[4];
    const float* gru_br = (const float*)d_in[5];
    const float* w1     = (const float*)d_in[6];
    const float* b1     = (const float*)d_in[7];
    const float* w2     = (const float*)d_in[8];
    const float* b2     = (const float*)d_in[9];
    float* out = (float*)d_out;

    float* tablep = nullptr; cudaGetSymbolAddress((void**)&tablep, g_table);
    float* hsp    = nullptr; cudaGetSymbolAddress((void**)&hsp,    g_hs);
    float* logp   = nullptr; cudaGetSymbolAddress((void**)&logp,   g_logits);
    bf16* embs = nullptr; cudaGetSymbolAddress((void**)&embs, g_embs);
    bf16* gukt = nullptr; cudaGetSymbolAddress((void**)&gukt, g_gukt);
    bf16* hss  = nullptr; cudaGetSymbolAddress((void**)&hss,  g_hss);
    bf16* w1t  = nullptr; cudaGetSymbolAddress((void**)&w1t,  g_w1t);
    bf16* ds   = nullptr; cudaGetSymbolAddress((void**)&ds,   g_ds);
    bf16* w2t  = nullptr; cudaGetSymbolAddress((void**)&w2t,  g_w2t);

    static int smem_set = 0;
    if (!smem_set) {
        cudaFuncSetAttribute(gru_persist_tc, cudaFuncAttributeMaxDynamicSharedMemorySize,
                             GRU_SMEM_BYTES);
        smem_set = 1;
    }

    // 0) split/transpose prep
    split_rows<<<(NV*NE + 255)/256, 256>>>(emb, NV, NE, embs);
    { dim3 g((NG+31)/32, (NE+31)/32);  transp_split<<<g, 256>>>(gru_k, NE, NG, gukt); }
    { dim3 g((ND+31)/32, (NH+31)/32);  transp_split<<<g, 256>>>(w1, NH, ND, w1t); }
    { dim3 g((NV+31)/32, (ND+31)/32);  transp_split<<<g, 256>>>(w2, ND, NV, w2t); }

    // 1) table = emb @ gru_k + gru_bi
    {
        dim3 grid(NG/128, (NV + 127)/128);
        gemm_bf16s<<<grid, 256>>>(embs, 3*NE, gukt, 3*NE, NV, NG, 3*NE,
                                  gru_bi, 0, tablep, NG, nullptr, 0);
    }

    // 2) tensor-core persistent GRU
    reset_bar<<<1, 1>>>();
    gru_persist_tc<<<NBLK, 256, GRU_SMEM_BYTES>>>(tokens, gru_rk, gru_br);

    // 2.5) split hs for head
    split_rows<<<(NB*NT*NH + 255)/256, 256>>>(hsp, NB*NT, NH, hss);

    // 3) d' = split(relu(hs @ w1 + b1))
    {
        dim3 grid(1, (NB*NT)/128);
        gemm_bf16s<<<grid, 256>>>(hss, 3*NH, w1t, 3*NH, NB*NT, ND, 3*NH,
                                  b1, 1, nullptr, 0, ds, ND);
    }

    // 4) logits = d @ w2 + b2
    {
        dim3 grid((NV + 127)/128, (NB*NT)/128);
        gemm_bf16s<<<grid, 256>>>(ds, 3*ND, w2t, 3*ND, NB*NT, NV, 3*ND,
                                  b2, 0, logp, NV, nullptr, 0);
    }

    // 5) softmax
    softmax_rows<<<NB*NT, 256>>>(out);
}

// round 8
// speedup vs baseline: 2.6260x; 1.1525x over previous
#include <cuda_runtime.h>
#include <cuda_bf16.h>
#include <math.h>
#include <cstdint>

#define NB 128
#define NT 128
#define NV 10000
#define NE 256
#define NH 1024
#define ND 128
#define NG 3072   // 3*NH

#define NBLK 128

typedef unsigned long long u64;
typedef __nv_bfloat16 bf16;

// ---------------- scratch ----------------
__device__ float g_table[(size_t)NV * NG];
__device__ float g_hs[(size_t)NB * NT * NH];
__device__ float g_logits[(size_t)NB * NT * NV];
__device__ unsigned g_barcnt;
__device__ bf16 g_hsplit[2][(size_t)NB * 2048];       // [parity][b][hi(1024)|lo(1024)]
// split operands for head GEMMs
__device__ bf16 g_embs[(size_t)NV * (3*NE)];
__device__ bf16 g_gukt[(size_t)NG * (3*NE)];
__device__ bf16 g_hss [(size_t)NB*NT * (3*NH)];
__device__ bf16 g_w1t [(size_t)ND * (3*NH)];
__device__ bf16 g_ds  [(size_t)NB*NT * (3*ND)];
__device__ bf16 g_w2t [(size_t)NV * (3*ND)];

// ================= split/transpose prep (R4 verbatim) =================
__global__ __launch_bounds__(256)
void split_rows(const float* __restrict__ src, int M, int K, bf16* __restrict__ dst)
{
    size_t idx = (size_t)blockIdx.x * 256 + threadIdx.x;
    if (idx >= (size_t)M * K) return;
    int m = (int)(idx / K), k = (int)(idx % K);
    float x = src[idx];
    bf16 h = __float2bfloat16(x);
    bf16 l = __float2bfloat16(x - __bfloat162float(h));
    bf16* d = dst + (size_t)m * 3 * K;
    d[k] = h; d[K + k] = h; d[2*K + k] = l;
}

__global__ __launch_bounds__(256)
void transp_split(const float* __restrict__ src, int K, int N, bf16* __restrict__ dst)
{
    __shared__ float tile[32][33];
    int k0 = blockIdx.y * 32, n0 = blockIdx.x * 32;
    int tx = threadIdx.x & 31, ty = threadIdx.x >> 5;
    for (int i = ty; i < 32; i += 8) {
        int k = k0 + i, n = n0 + tx;
        tile[i][tx] = (k < K && n < N) ? src[(size_t)k * N + n] : 0.0f;
    }
    __syncthreads();
    for (int i = ty; i < 32; i += 8) {
        int n = n0 + i, k = k0 + tx;
        if (n < N && k < K) {
            float x = tile[tx][i];
            bf16 h = __float2bfloat16(x);
            bf16 l = __float2bfloat16(x - __bfloat162float(h));
            bf16* d = dst + (size_t)n * 3 * K;
            d[k] = h; d[K + k] = l; d[2*K + k] = h;
        }
    }
}

// ================= bf16 mma.sync GEMM for head (R4 verbatim) =================
#define GSTR 40

__global__ __launch_bounds__(256)
void gemm_bf16s(const bf16* __restrict__ A, int lda,
                const bf16* __restrict__ Bt, int ldb,
                int M, int N, int K3,
                const float* __restrict__ bias, int relu,
                float* __restrict__ C, int ldc,
                bf16* __restrict__ Cs, int Kout)
{
    __shared__ bf16 As[128 * GSTR];
    __shared__ bf16 Bs[128 * GSTR];

    const int tid  = threadIdx.x;
    const int lane = tid & 31;
    const int warp = tid >> 5;
    const int bm0 = blockIdx.y * 128, bn0 = blockIdx.x * 128;
    const int wm0 = (warp >> 2) * 64, wn0 = (warp & 3) * 32;

    float c[4][4][4];
#pragma unroll
    for (int mi = 0; mi < 4; mi++)
#pragma unroll
        for (int ni = 0; ni < 4; ni++)
#pragma unroll
            for (int q = 0; q < 4; q++) c[mi][ni][q] = 0.0f;

    for (int k0 = 0; k0 < K3; k0 += 32) {
#pragma unroll
        for (int it = 0; it < 2; it++) {
            int idx = tid + 256 * it;
            int r = idx >> 2, seg = (idx & 3) * 8;
            int gm = bm0 + r; if (gm > M-1) gm = M-1;
            uint4 v = *(const uint4*)&A[(size_t)gm * lda + k0 + seg];
            *(uint4*)&As[r * GSTR + seg] = v;
        }
#pragma unroll
        for (int it = 0; it < 2; it++) {
            int idx = tid + 256 * it;
            int r = idx >> 2, seg = (idx & 3) * 8;
            int gn = bn0 + r; if (gn > N-1) gn = N-1;
            uint4 v = *(const uint4*)&Bt[(size_t)gn * ldb + k0 + seg];
            *(uint4*)&Bs[r * GSTR + seg] = v;
        }
        __syncthreads();

#pragma unroll
        for (int ks = 0; ks < 2; ks++) {
            unsigned bfr[4][2];
#pragma unroll
            for (int ni = 0; ni < 4; ni++) {
                const bf16* p = &Bs[(wn0 + ni*8 + (lane >> 2)) * GSTR + ks*16 + (lane & 3)*2];
                bfr[ni][0] = *(const unsigned*)p;
                bfr[ni][1] = *(const unsigned*)(p + 8);
            }
#pragma unroll
            for (int mi = 0; mi < 4; mi++) {
                unsigned a0, a1, a2, a3;
                unsigned saddr = (unsigned)__cvta_generic_to_shared(
                    &As[(wm0 + mi*16 + (lane & 15)) * GSTR + ks*16 + (lane >> 4)*8]);
                asm volatile("ldmatrix.sync.aligned.m8n8.x4.shared.b16 {%0,%1,%2,%3},[%4];"
                             : "=r"(a0), "=r"(a1), "=r"(a2), "=r"(a3) : "r"(saddr));
#pragma unroll
                for (int ni = 0; ni < 4; ni++) {
                    asm volatile(
                        "mma.sync.aligned.m16n8k16.row.col.f32.bf16.bf16.f32 "
                        "{%0,%1,%2,%3},{%4,%5,%6,%7},{%8,%9},{%0,%1,%2,%3};"
                        : "+f"(c[mi][ni][0]), "+f"(c[mi][ni][1]),
                          "+f"(c[mi][ni][2]), "+f"(c[mi][ni][3])
                        : "r"(a0), "r"(a1), "r"(a2), "r"(a3),
                          "r"(bfr[ni][0]), "r"(bfr[ni][1]));
                }
            }
        }
        __syncthreads();
    }

#pragma unroll
    for (int mi = 0; mi < 4; mi++) {
#pragma unroll
        for (int ni = 0; ni < 4; ni++) {
            int r0  = bm0 + wm0 + mi*16 + (lane >> 2);
            int col = bn0 + wn0 + ni*8 + (lane & 3)*2;
#pragma unroll
            for (int q = 0; q < 4; q++) {
                int gm = r0 + (q >> 1) * 8;
                int gn = col + (q & 1);
                if (gm >= M || gn >= N) continue;
                float v = c[mi][ni][q];
                if (bias) v += bias[gn];
                if (relu) v = fmaxf(v, 0.0f);
                if (C) C[(size_t)gm * ldc + gn] = v;
                if (Cs) {
                    bf16 h = __float2bfloat16(v);
                    bf16 l = __float2bfloat16(v - __bfloat162float(h));
                    bf16* d = Cs + (size_t)gm * 3 * Kout;
                    d[gn] = h; d[Kout + gn] = h; d[2*Kout + gn] = l;
                }
            }
        }
    }
}

// ================= persistent GRU (mma.sync, pipelined) =================
__global__ void reset_bar() { g_barcnt = 0u; }

#define W_STR 2056                  // bf16 stride of weight rows (rows on distinct banks)
#define A_LD  136                   // bf16 stride of staged h rows
#define W_FLOATS_B (24 * W_STR * 2)           // 98688 bytes
#define ABUF_B     (128 * A_LD * 2)           // 34816 bytes per buffer
#define GRU_SMEM_BYTES (W_FLOATS_B + 2 * ABUF_B + 96 + 512 + 64)

__device__ __forceinline__ void mma16816(float c[4], unsigned a0, unsigned a1,
                                         unsigned a2, unsigned a3,
                                         unsigned b0, unsigned b1) {
    asm volatile(
        "mma.sync.aligned.m16n8k16.row.col.f32.bf16.bf16.f32 "
        "{%0,%1,%2,%3},{%4,%5,%6,%7},{%8,%9},{%0,%1,%2,%3};"
        : "+f"(c[0]), "+f"(c[1]), "+f"(c[2]), "+f"(c[3])
        : "r"(a0), "r"(a1), "r"(a2), "r"(a3), "r"(b0), "r"(b1));
}

__global__ __launch_bounds__(256, 1)
void gru_persist_tc(const int* __restrict__ tokens,
                    const float* __restrict__ gru_rk,
                    const float* __restrict__ br)
{
    extern __shared__ char smc[];
    bf16*  w_s   = (bf16*)smc;                              // [24][W_STR]: [hi|lo]
    bf16*  Asb   = (bf16*)(smc + W_FLOATS_B);               // 2 x [128][A_LD]
    float* br_s  = (float*)(smc + W_FLOATS_B + 2 * ABUF_B);
    int*   tok_s = (int*)(smc + W_FLOATS_B + 2 * ABUF_B + 96);

    const int tid  = threadIdx.x;
    const int bid  = blockIdx.x;
    const int lane = tid & 31;
    const int warp = tid >> 5;
    const int jb   = bid * 8;
    const int m0   = warp * 16;

    // resident split weights: w_s[c][k], c = gate*8 + col, k in [hi 1024 | lo 1024]
    for (int idx = tid; idx < 24 * 2048; idx += 256) {
        int c = idx >> 11, k = idx & 2047;
        float v = gru_rk[(size_t)(k & 1023) * NG + (c >> 3) * NH + jb + (c & 7)];
        bf16 hv = __float2bfloat16(v);
        w_s[c * W_STR + k] = (k < 1024) ? hv : __float2bfloat16(v - __bfloat162float(hv));
    }
    if (tid < 24) br_s[tid] = br[(tid >> 3) * NH + jb + (tid & 7)];
    __syncthreads();

    const int j0 = (lane & 3) * 2;
    const float brz0 = br_s[j0],      brz1 = br_s[j0 + 1];
    const float brr0 = br_s[8 + j0],  brr1 = br_s[8 + j0 + 1];
    const float brh0 = br_s[16 + j0], brh1 = br_s[16 + j0 + 1];

    const int s_seg = (tid & 15) * 8;    // k segment (8 bf16)
    const int s_r0  = tid >> 4;          // row base, +16 per it

    for (int t = 0; t < NT; t++) {
        float acc[3][4];
#pragma unroll
        for (int g = 0; g < 3; g++)
#pragma unroll
            for (int q = 0; q < 4; q++) acc[g][q] = 0.0f;

        if (tid < 128) tok_s[tid] = tokens[tid * NT + t];

        if (t > 0) {
            const bf16* hsrc = g_hsplit[(t + 1) & 1];
            uint4 pre[8];

            // prologue: stage chunk 0 into buf0
#pragma unroll
            for (int it = 0; it < 8; it++)
                pre[it] = __ldcg((const uint4*)&hsrc[(size_t)(s_r0 + 16*it) * 2048 + s_seg]);
#pragma unroll
            for (int it = 0; it < 8; it++)
                *(uint4*)&Asb[(s_r0 + 16*it) * A_LD + s_seg] = pre[it];
            __syncthreads();

            for (int c = 0; c < 16; c++) {
                // 1) prefetch chunk c+1 into regs (overlaps with mma below)
                if (c < 15) {
                    const int cb = (c + 1) * 128;
#pragma unroll
                    for (int it = 0; it < 8; it++)
                        pre[it] = __ldcg((const uint4*)&hsrc[(size_t)(s_r0 + 16*it) * 2048 + cb + s_seg]);
                }
                // 2) mma on chunk c
                const bf16* ab = Asb + (c & 1) * 128 * A_LD;
                const bool hi = (c < 8);
                const int kg = (hi ? c : c - 8) * 128;   // k offset within w_hi region
#pragma unroll
                for (int ks2 = 0; ks2 < 4; ks2++) {
                    // A frags for two k16 steps
                    unsigned a[2][4];
#pragma unroll
                    for (int s = 0; s < 2; s++) {
                        unsigned sa = (unsigned)__cvta_generic_to_shared(
                            &ab[(m0 + (lane & 15)) * A_LD + ks2*32 + s*16 + (lane >> 4)*8]);
                        asm volatile("ldmatrix.sync.aligned.m8n8.x4.shared.b16 {%0,%1,%2,%3},[%4];"
                                     : "=r"(a[s][0]), "=r"(a[s][1]), "=r"(a[s][2]), "=r"(a[s][3])
                                     : "r"(sa));
                    }
                    const int kw = kg + ks2 * 32;
                    // B via ldmatrix.x4: tiles (gate rows, k+0..7 / +8..15 / +16..23 / +24..31)
#pragma unroll
                    for (int g = 0; g < 3; g++) {
                        unsigned b4[4];
                        unsigned sb = (unsigned)__cvta_generic_to_shared(
                            &w_s[(g*8 + (lane & 7)) * W_STR + kw + (lane >> 3)*8]);
                        asm volatile("ldmatrix.sync.aligned.m8n8.x4.shared.b16 {%0,%1,%2,%3},[%4];"
                                     : "=r"(b4[0]), "=r"(b4[1]), "=r"(b4[2]), "=r"(b4[3])
                                     : "r"(sb));
                        mma16816(acc[g], a[0][0], a[0][1], a[0][2], a[0][3], b4[0], b4[1]);
                        mma16816(acc[g], a[1][0], a[1][1], a[1][2], a[1][3], b4[2], b4[3]);
                    }
                    if (hi) {   // h_hi . w_lo (reuse A frags)
#pragma unroll
                        for (int g = 0; g < 3; g++) {
                            unsigned b4[4];
                            unsigned sb = (unsigned)__cvta_generic_to_shared(
                                &w_s[(g*8 + (lane & 7)) * W_STR + 1024 + kw + (lane >> 3)*8]);
                            asm volatile("ldmatrix.sync.aligned.m8n8.x4.shared.b16 {%0,%1,%2,%3},[%4];"
                                         : "=r"(b4[0]), "=r"(b4[1]), "=r"(b4[2]), "=r"(b4[3])
                                         : "r"(sb));
                            mma16816(acc[g], a[0][0], a[0][1], a[0][2], a[0][3], b4[0], b4[1]);
                            mma16816(acc[g], a[1][0], a[1][1], a[1][2], a[1][3], b4[2], b4[3]);
                        }
                    }
                }
                __syncthreads();   // all warps done with buf (c&1) mma; safe to write other buf
                // 3) store prefetched chunk c+1
                if (c < 15) {
                    bf16* dst = Asb + ((c + 1) & 1) * 128 * A_LD;
#pragma unroll
                    for (int it = 0; it < 8; it++)
                        *(uint4*)&dst[(s_r0 + 16*it) * A_LD + s_seg] = pre[it];
                    __syncthreads();
                }
            }
        } else {
            __syncthreads();
        }

        // ---- gates: lane owns rows m0+(lane>>2)+{0,8}, cols jb+j0, jb+j0+1
        bf16* hout = g_hsplit[t & 1];
#pragma unroll
        for (int rr = 0; rr < 2; rr++) {
            int b = m0 + (lane >> 2) + rr * 8;
            int tok = tok_s[b];
            const float* tab = g_table + (size_t)tok * NG + jb;
            float h2[2];
#pragma unroll
            for (int qq = 0; qq < 2; qq++) {
                int j = j0 + qq;
                float rz = acc[0][rr*2 + qq] + (qq ? brz1 : brz0);
                float rrg= acc[1][rr*2 + qq] + (qq ? brr1 : brr0);
                float rh = acc[2][rr*2 + qq] + (qq ? brh1 : brh0);
                float xz = tab[j], xr = tab[NH + j], xh = tab[2*NH + j];
                float z  = 1.0f / (1.0f + expf(-(xz + rz)));
                float r  = 1.0f / (1.0f + expf(-(xr + rrg)));
                float hh = tanhf(xh + r * rh);
                float hp = (t > 0) ? g_hs[((size_t)b * NT + (t-1)) * NH + jb + j] : 0.0f;
                h2[qq] = z * hp + (1.0f - z) * hh;
            }
            *(float2*)&g_hs[((size_t)b * NT + t) * NH + jb + j0] = make_float2(h2[0], h2[1]);
            bf16 h0h = __float2bfloat16(h2[0]);
            bf16 h1h = __float2bfloat16(h2[1]);
            bf16 h0l = __float2bfloat16(h2[0] - __bfloat162float(h0h));
            bf16 h1l = __float2bfloat16(h2[1] - __bfloat162float(h1h));
            __nv_bfloat162 ph; ph.x = h0h; ph.y = h1h;
            __nv_bfloat162 pl; pl.x = h0l; pl.y = h1l;
            *(__nv_bfloat162*)&hout[(size_t)b * 2048 + jb + j0]        = ph;
            *(__nv_bfloat162*)&hout[(size_t)b * 2048 + 1024 + jb + j0] = pl;
        }

        // ---- grid barrier
        __syncthreads();
        if (tid == 0) {
            __threadfence();
            atomicAdd(&g_barcnt, 1u);
            const unsigned target = (unsigned)NBLK * (unsigned)(t + 1);
            while (atomicAdd(&g_barcnt, 0u) < target) { }
        }
        __syncthreads();
    }
}

// ================= softmax (R2 verbatim) =================
__global__ __launch_bounds__(256)
void softmax_rows(float* __restrict__ out)
{
    __shared__ float row[NV];
    __shared__ float red[256];
    const int tid = threadIdx.x;
    const size_t r0 = (size_t)blockIdx.x * NV;

    float m = -1e30f;
    for (int v = tid; v < NV; v += 256) {
        float x = g_logits[r0 + v];
        row[v] = x;
        m = fmaxf(m, x);
    }
    red[tid] = m; __syncthreads();
    for (int s = 128; s > 0; s >>= 1) {
        if (tid < s) red[tid] = fmaxf(red[tid], red[tid + s]);
        __syncthreads();
    }
    const float smax = red[0];
    __syncthreads();

    float sum = 0.0f;
    for (int v = tid; v < NV; v += 256) {
        float e = expf((row[v] - smax) * 50.0f);
        row[v] = e;
        sum += e;
    }
    red[tid] = sum; __syncthreads();
    for (int s = 128; s > 0; s >>= 1) {
        if (tid < s) red[tid] += red[tid + s];
        __syncthreads();
    }
    const float inv = 1.0f / red[0];
    for (int v = tid; v < NV; v += 256)
        out[r0 + v] = row[v] * inv;
}

// ================= launch =================
extern "C" void kernel_launch(void* const* d_in, const int* in_sizes, int n_in,
                              void* d_out, int out_size)
{
    const int*   tokens = (const int*)  d_in[0];
    const float* emb    = (const float*)d_in[1];
    const float* gru_k  = (const float*)d_in[2];
    const float* gru_rk = (const float*)d_in[3];
    const float* gru_bi = (const float*)d_in[4];
    const float* gru_br = (const float*)d_in[5];
    const float* w1     = (const float*)d_in[6];
    const float* b1     = (const float*)d_in[7];
    const float* w2     = (const float*)d_in[8];
    const float* b2     = (const float*)d_in[9];
    float* out = (float*)d_out;

    float* tablep = nullptr; cudaGetSymbolAddress((void**)&tablep, g_table);
    float* hsp    = nullptr; cudaGetSymbolAddress((void**)&hsp,    g_hs);
    float* logp   = nullptr; cudaGetSymbolAddress((void**)&logp,   g_logits);
    bf16* embs = nullptr; cudaGetSymbolAddress((void**)&embs, g_embs);
    bf16* gukt = nullptr; cudaGetSymbolAddress((void**)&gukt, g_gukt);
    bf16* hss  = nullptr; cudaGetSymbolAddress((void**)&hss,  g_hss);
    bf16* w1t  = nullptr; cudaGetSymbolAddress((void**)&w1t,  g_w1t);
    bf16* ds   = nullptr; cudaGetSymbolAddress((void**)&ds,   g_ds);
    bf16* w2t  = nullptr; cudaGetSymbolAddress((void**)&w2t,  g_w2t);

    static int smem_set = 0;
    if (!smem_set) {
        cudaFuncSetAttribute(gru_persist_tc, cudaFuncAttributeMaxDynamicSharedMemorySize,
                             GRU_SMEM_BYTES);
        smem_set = 1;
    }

    // 0) split/transpose prep
    split_rows<<<(NV*NE + 255)/256, 256>>>(emb, NV, NE, embs);
    { dim3 g((NG+31)/32, (NE+31)/32);  transp_split<<<g, 256>>>(gru_k, NE, NG, gukt); }
    { dim3 g((ND+31)/32, (NH+31)/32);  transp_split<<<g, 256>>>(w1, NH, ND, w1t); }
    { dim3 g((NV+31)/32, (ND+31)/32);  transp_split<<<g, 256>>>(w2, ND, NV, w2t); }

    // 1) table = emb @ gru_k + gru_bi
    {
        dim3 grid(NG/128, (NV + 127)/128);
        gemm_bf16s<<<grid, 256>>>(embs, 3*NE, gukt, 3*NE, NV, NG, 3*NE,
                                  gru_bi, 0, tablep, NG, nullptr, 0);
    }

    // 2) persistent GRU (mma.sync, pipelined)
    reset_bar<<<1, 1>>>();
    gru_persist_tc<<<NBLK, 256, GRU_SMEM_BYTES>>>(tokens, gru_rk, gru_br);

    // 2.5) split hs for head
    split_rows<<<(NB*NT*NH + 255)/256, 256>>>(hsp, NB*NT, NH, hss);

    // 3) d' = split(relu(hs @ w1 + b1))
    {
        dim3 grid(1, (NB*NT)/128);
        gemm_bf16s<<<grid, 256>>>(hss, 3*NH, w1t, 3*NH, NB*NT, ND, 3*NH,
                                  b1, 1, nullptr, 0, ds, ND);
    }

    // 4) logits = d @ w2 + b2
    {
        dim3 grid((NV + 127)/128, (NB*NT)/128);
        gemm_bf16s<<<grid, 256>>>(ds, 3*ND, w2t, 3*ND, NB*NT, NV, 3*ND,
                                  b2, 0, logp, NV, nullptr, 0);
    }

    // 5) softmax
    softmax_rows<<<NB*NT, 256>>>(out);
}